// round 2
// baseline (speedup 1.0000x reference)
#include <cuda_runtime.h>
#include <cuda_bf16.h>

#define NN 1024

// rho_out = U rho U^T with U = kron(Rot(alpha), Rot(beta)) on bits (5, 0).
// alpha = sum of even-layer angles, beta = sum of odd-layer angles.
// 4 threads per 4x4 coset group {x, x^1, x^32, x^33}: each computes ONE
// output row of the group (loads the full 4x4 G; siblings share cache lines).
__global__ __launch_bounds__(256) void vqc_collapse_kernel(
    const float* __restrict__ rho,
    const float* __restrict__ ang,
    float* __restrict__ out)
{
    float alpha = ang[0] + ang[2] + ang[4] + ang[6] +
                  ang[8] + ang[10] + ang[12] + ang[14];
    float beta  = ang[1] + ang[3] + ang[5] + ang[7] +
                  ang[9] + ang[11] + ang[13] + ang[15];
    float sa, ca, sb, cb;
    sincosf(alpha, &sa, &ca);
    sincosf(beta,  &sb, &cb);

    const float A[2][2] = { { ca, -sa }, { sa, ca } };
    const float B[2][2] = { { cb, -sb }, { sb, cb } };

    float U[4][4];
#pragma unroll
    for (int i = 0; i < 4; i++)
#pragma unroll
        for (int j = 0; j < 4; j++)
            U[i][j] = A[i >> 1][j >> 1] * B[i & 1][j & 1];

    // tid bits: [ gr(8) | gc_hi(4) | ri(2) | gc_lo(4) ]  -> 262144 threads
    int t = blockIdx.x * blockDim.x + threadIdx.x;
    int gc_lo = t & 15;
    int ri    = (t >> 4) & 3;
    int gc_hi = (t >> 6) & 15;
    int gr    = t >> 10;

    // Expand group indices: insert zero bits at positions 0 and 5.
    int r0 = ((gr & 15) << 1) | ((gr >> 4) << 6);
    int c0 = (gc_lo << 1) | (gc_hi << 6);

    const int off[4] = { 0, 1, 32, 33 };

    // Gather the full 4x4 group (rows shared with sibling lanes via L1)
    float G[4][4];
#pragma unroll
    for (int k = 0; k < 4; k++) {
        const float* row = rho + (size_t)(r0 + off[k]) * NN;
        float2 a = *reinterpret_cast<const float2*>(row + c0);
        float2 b = *reinterpret_cast<const float2*>(row + c0 + 32);
        G[k][0] = a.x; G[k][1] = a.y; G[k][2] = b.x; G[k][3] = b.y;
    }

    // Only row ri of M = U*G
    float m[4];
#pragma unroll
    for (int l = 0; l < 4; l++)
        m[l] = U[ri][0] * G[0][l] + U[ri][1] * G[1][l]
             + U[ri][2] * G[2][l] + U[ri][3] * G[3][l];

    // Row ri of O = M * U^T
    float o[4];
#pragma unroll
    for (int j = 0; j < 4; j++)
        o[j] = m[0] * U[j][0] + m[1] * U[j][1]
             + m[2] * U[j][2] + m[3] * U[j][3];

    float* orow = out + (size_t)(r0 + off[ri]) * NN;
    *reinterpret_cast<float2*>(orow + c0)      = make_float2(o[0], o[1]);
    *reinterpret_cast<float2*>(orow + c0 + 32) = make_float2(o[2], o[3]);
}

extern "C" void kernel_launch(void* const* d_in, const int* in_sizes, int n_in,
                              void* d_out, int out_size)
{
    const float* rho = (const float*)d_in[0];
    const float* ang = (const float*)d_in[1];
    float* out = (float*)d_out;

    // 262144 threads: 4 per 4x4 coset group
    vqc_collapse_kernel<<<1024, 256>>>(rho, ang, out);
}